// round 7
// baseline (speedup 1.0000x reference)
#include <cuda_runtime.h>
#include <cstdint>

// Problem constants
#define BATCH 2
#define A_    2
#define C_    10
#define HW_   1024
#define NBOX  2048
#define TILE  128
#define LOG2E 1.4426950408889634f
#define PI_F  3.14159265358979323846f

// Output layout: out_scores [0,40960) | bbox [40960,69632) | pp [69632,131072)
#define OUT_BBOX 40960
#define OUT_PP   69632

// ---------------- scratch tables (SoA-group layouts) ----------------
__device__ __align__(16) float4 g_bev4[BATCH * 2 * HW_];
__device__ __align__(16) float4 g_pc4[BATCH * 8 * HW_];
__device__ __align__(8)  float  g_p0[BATCH * HW_ * 10];
__device__ float g_scinv[BATCH * C_];

// ---------------- helpers ----------------
typedef unsigned long long ull;
__device__ __forceinline__ float ex2(float x) {
    float y; asm("ex2.approx.f32 %0, %1;" : "=f"(y) : "f"(x)); return y;
}
__device__ __forceinline__ float rcpf(float x) {
    float y; asm("rcp.approx.f32 %0, %1;" : "=f"(y) : "f"(x)); return y;
}
__device__ __forceinline__ ull pk(float a, float b) {
    ull r; asm("mov.b64 %0, {%1,%2};" : "=l"(r) : "f"(a), "f"(b)); return r;
}
__device__ __forceinline__ void upk(ull v, float& a, float& b) {
    asm("mov.b64 {%0,%1}, %2;" : "=f"(a), "=f"(b) : "l"(v));
}
__device__ __forceinline__ ull mul2(ull a, ull b) {
    ull r; asm("mul.rn.f32x2 %0, %1, %2;" : "=l"(r) : "l"(a), "l"(b)); return r;
}
__device__ __forceinline__ ull fma2(ull a, ull b, ull c) {
    ull r; asm("fma.rn.f32x2 %0, %1, %2, %3;" : "=l"(r) : "l"(a), "l"(b), "l"(c)); return r;
}
__device__ __forceinline__ ull add2(ull a, ull b) {
    ull r; asm("add.rn.f32x2 %0, %1, %2;" : "=l"(r) : "l"(a), "l"(b)); return r;
}
__device__ __forceinline__ void cpasync16(uint32_t saddr, const void* g) {
    asm volatile("cp.async.cg.shared.global [%0], [%1], 16;" :: "r"(saddr), "l"(g));
}

// ---------------------------------------------------------------------------
// K1 fused: prep tables (blocks 0..7) + score softmax denominators (8..27)
// ---------------------------------------------------------------------------
__global__ void k_fused(const float* __restrict__ scores,
                        const float* __restrict__ pp,
                        const float* __restrict__ dec) {
    int blk = blockIdx.x;
    int tid = threadIdx.x;

    if (blk < 8) {
        int idx = blk * 256 + tid;
        int b = idx >> 10;
        int hw = idx & (HW_ - 1);

        float x1a[2], y1a[2], x2a[2], y2a[2], area[2];
#pragma unroll
        for (int a = 0; a < 2; a++) {
            const float* d7 = dec + ((size_t)b * NBOX + hw * 2 + a) * 7;
            float x = d7[0], y = d7[1], dx = d7[3], dy = d7[4], yaw = d7[6];
            float normed = fabsf(yaw - floorf(yaw / PI_F + 0.5f) * PI_F);
            bool sw = normed > 0.25f * PI_F;
            float w = sw ? dy : dx;
            float h = sw ? dx : dy;
            x1a[a] = x - 0.5f * w; y1a[a] = y - 0.5f * h;
            x2a[a] = x + 0.5f * w; y2a[a] = y + 0.5f * h;
            area[a] = (x2a[a] - x1a[a]) * (y2a[a] - y1a[a]);
        }
        float4* bv = g_bev4 + (size_t)b * 2 * HW_ + hw;
        bv[0]    = make_float4(x1a[0], x1a[1], y1a[0], y1a[1]);
        bv[HW_]  = make_float4(x2a[0], x2a[1], y2a[0], y2a[1]);

        float e[C_][2], p1[C_];
#pragma unroll
        for (int c = 0; c < C_; c++) {
            e[c][0] = __expf(scores[((b * A_ + 0) * C_ + c) * HW_ + hw]);
            e[c][1] = __expf(scores[((b * A_ + 1) * C_ + c) * HW_ + hw]);
            p1[c]   = pp[((size_t)b * 30 + c * 3 + 1) * HW_ + hw];
            g_p0[(size_t)idx * 10 + c] =
                pp[((size_t)b * 30 + c * 3) * HW_ + hw] * LOG2E;
        }
        float4* pc = g_pc4 + (size_t)b * 8 * HW_ + hw;
#pragma unroll
        for (int k = 0; k < 5; k++)
            pc[k * HW_] = make_float4(e[2 * k][0], e[2 * k + 1][0],
                                      e[2 * k][1], e[2 * k + 1][1]);
        pc[5 * HW_] = make_float4(p1[0], p1[1], p1[2], p1[3]);
        pc[6 * HW_] = make_float4(p1[4], p1[5], p1[6], p1[7]);
        pc[7 * HW_] = make_float4(p1[8], p1[9], area[0], area[1]);
    } else {
        int s = blk - 8;
        int b = s / C_, c = s % C_;
        __shared__ float red[256];
        float acc = 0.f;
        for (int m = tid; m < NBOX; m += 256) {
            int a = m & 1, hw = m >> 1;
            acc += __expf(scores[((b * A_ + a) * C_ + c) * HW_ + hw]);
        }
        red[tid] = acc;
        __syncthreads();
#pragma unroll
        for (int o = 128; o > 0; o >>= 1) {
            if (tid < o) red[tid] += red[tid + o];
            __syncthreads();
        }
        if (tid == 0) g_scinv[b * C_ + c] = 1.0f / red[0];
    }
}

// ---------------------------------------------------------------------------
// K2 main: one warp handles TWO n-cells (hwn, hwn+512); m-tiles in smem are
//          loaded once and reused for both. Blocks >= 256 do pass-through.
// ---------------------------------------------------------------------------
__device__ __forceinline__ float iou1(float ax1, float ay1, float ax2, float ay2, float aa,
                                      float bx1, float by1, float bx2, float by2, float ba) {
    float ltx = fmaxf(ax1, bx1);
    float lty = fmaxf(ay1, by1);
    float rbx = fminf(ax2, bx2);
    float rby = fminf(ay2, by2);
    float w = fmaxf(rbx - ltx, 0.f);
    float h = fmaxf(rby - lty, 0.f);
    float inter = w * h;
    float uni = fmaxf(aa + ba - inter, 1e-6f);
    return inter * LOG2E * rcpf(uni);
}

__global__ void __launch_bounds__(128, 3) k_main(
        const float* __restrict__ bbox, const float* __restrict__ pp,
        float* __restrict__ out) {
    if (blockIdx.x >= 256) {
        // pass-through copies: 88 blocks * 256 float4 = 22528 f4
        int base = (blockIdx.x - 256) * 256 + threadIdx.x;
#pragma unroll
        for (int r = 0; r < 2; r++) {
            int i = base + r * 128;
            if (i < 7168)
                ((float4*)(out + OUT_BBOX))[i] = ((const float4*)bbox)[i];
            else
                ((float4*)(out + OUT_PP))[i - 7168] = ((const float4*)pp)[i - 7168];
        }
        return;
    }

    __shared__ __align__(16) ulonglong2 sb[2][2 * TILE];  // bev groups
    __shared__ __align__(16) ulonglong2 sp[2][8 * TILE];  // pc groups

    int tid = threadIdx.x;
    int lane = tid & 31;
    int gw = blockIdx.x * 4 + (tid >> 5);   // 0..1023
    int b = gw >> 9;
    int nid = gw & 511;
    int hwnA = nid;
    int hwnB = nid + 512;
    int gwA = b * HW_ + hwnA;
    int gwB = b * HW_ + hwnB;

    // n-side invariants for both n-cells
    float4 ag0 = g_bev4[(size_t)b * 2 * HW_ + hwnA];
    float4 ag1 = g_bev4[(size_t)b * 2 * HW_ + HW_ + hwnA];
    float4 ag7 = g_pc4[(size_t)b * 8 * HW_ + 7 * HW_ + hwnA];
    float4 cg0 = g_bev4[(size_t)b * 2 * HW_ + hwnB];
    float4 cg1 = g_bev4[(size_t)b * 2 * HW_ + HW_ + hwnB];
    float4 cg7 = g_pc4[(size_t)b * 8 * HW_ + 7 * HW_ + hwnB];

    ull p0A[5], p0B[5];
#pragma unroll
    for (int k = 0; k < 5; k++) {
        float2 tA = *(const float2*)(g_p0 + (size_t)gwA * 10 + 2 * k);
        float2 tB = *(const float2*)(g_p0 + (size_t)gwB * 10 + 2 * k);
        p0A[k] = pk(tA.x, tA.y);
        p0B[k] = pk(tB.x, tB.y);
    }

    ull aA0[5], aA1[5], sA0[5], sA1[5];
    ull aB0[5], aB1[5], sB0[5], sB1[5];
#pragma unroll
    for (int k = 0; k < 5; k++) {
        aA0[k] = 0; aA1[k] = 0; sA0[k] = 0; sA1[k] = 0;
        aB0[k] = 0; aB1[k] = 0; sB0[k] = 0; sB1[k] = 0;
    }

    const float4* gb = g_bev4 + (size_t)b * 2 * HW_;
    const float4* gp = g_pc4 + (size_t)b * 8 * HW_;

    // prefetch tile 0
    {
        uint32_t sba = (uint32_t)__cvta_generic_to_shared(&sb[0][0]);
        uint32_t spa = (uint32_t)__cvta_generic_to_shared(&sp[0][0]);
#pragma unroll
        for (int g = 0; g < 2; g++)
            cpasync16(sba + (g * TILE + tid) * 16, gb + g * HW_ + tid);
#pragma unroll
        for (int g = 0; g < 8; g++)
            cpasync16(spa + (g * TILE + tid) * 16, gp + g * HW_ + tid);
        asm volatile("cp.async.commit_group;");
    }

    for (int t = 0; t < 8; t++) {
        if (t < 7) {
            int nb = (t + 1) & 1;
            uint32_t sba = (uint32_t)__cvta_generic_to_shared(&sb[nb][0]);
            uint32_t spa = (uint32_t)__cvta_generic_to_shared(&sp[nb][0]);
            int off = (t + 1) * TILE + tid;
#pragma unroll
            for (int g = 0; g < 2; g++)
                cpasync16(sba + (g * TILE + tid) * 16, gb + g * HW_ + off);
#pragma unroll
            for (int g = 0; g < 8; g++)
                cpasync16(spa + (g * TILE + tid) * 16, gp + g * HW_ + off);
            asm volatile("cp.async.commit_group;");
            asm volatile("cp.async.wait_group 1;");
        } else {
            asm volatile("cp.async.wait_group 0;");
        }
        __syncthreads();

        const ulonglong2* SB = sb[t & 1];
        const ulonglong2* SP = sp[t & 1];
#pragma unroll
        for (int j = 0; j < 4; j++) {
            int m = lane + j * 32;
            ulonglong2 bg0 = SB[m];
            ulonglong2 bg1 = SB[TILE + m];
            ulonglong2 G7  = SP[7 * TILE + m];

            float bx1a0, bx1a1, by1a0, by1a1, bx2a0, bx2a1, by2a0, by2a1;
            upk(bg0.x, bx1a0, bx1a1);
            upk(bg0.y, by1a0, by1a1);
            upk(bg1.x, bx2a0, bx2a1);
            upk(bg1.y, by2a0, by2a1);
            float am0, am1;
            upk(G7.y, am0, am1);

            // --- n = A ---
            float qA00 = iou1(ag0.x, ag0.z, ag1.x, ag1.z, ag7.z, bx1a0, by1a0, bx2a0, by2a0, am0);
            float qA01 = iou1(ag0.x, ag0.z, ag1.x, ag1.z, ag7.z, bx1a1, by1a1, bx2a1, by2a1, am1);
            float qA10 = iou1(ag0.y, ag0.w, ag1.y, ag1.w, ag7.w, bx1a0, by1a0, bx2a0, by2a0, am0);
            float qA11 = iou1(ag0.y, ag0.w, ag1.y, ag1.w, ag7.w, bx1a1, by1a1, bx2a1, by2a1, am1);
            float eA00 = ex2(qA00), eA01 = ex2(qA01);
            float eA10 = ex2(qA10), eA11 = ex2(qA11);
            ull eA00s = pk(eA00, eA00), eA01s = pk(eA01, eA01);
            ull eA10s = pk(eA10, eA10), eA11s = pk(eA11, eA11);
            ull esA0s = pk(eA00 + eA01, eA00 + eA01);
            ull esA1s = pk(eA10 + eA11, eA10 + eA11);

            // --- n = B ---
            float qB00 = iou1(cg0.x, cg0.z, cg1.x, cg1.z, cg7.z, bx1a0, by1a0, bx2a0, by2a0, am0);
            float qB01 = iou1(cg0.x, cg0.z, cg1.x, cg1.z, cg7.z, bx1a1, by1a1, bx2a1, by2a1, am1);
            float qB10 = iou1(cg0.y, cg0.w, cg1.y, cg1.w, cg7.w, bx1a0, by1a0, bx2a0, by2a0, am0);
            float qB11 = iou1(cg0.y, cg0.w, cg1.y, cg1.w, cg7.w, bx1a1, by1a1, bx2a1, by2a1, am1);
            float eB00 = ex2(qB00), eB01 = ex2(qB01);
            float eB10 = ex2(qB10), eB11 = ex2(qB11);
            ull eB00s = pk(eB00, eB00), eB01s = pk(eB01, eB01);
            ull eB10s = pk(eB10, eB10), eB11s = pk(eB11, eB11);
            ull esB0s = pk(eB00 + eB01, eB00 + eB01);
            ull esB1s = pk(eB10 + eB11, eB10 + eB11);

            ulonglong2 G5 = SP[5 * TILE + m];
            ulonglong2 G6 = SP[6 * TILE + m];
            ull p1p[5] = { G5.x, G5.y, G6.x, G6.y, G7.x };

#pragma unroll
            for (int k = 0; k < 5; k++) {
                ulonglong2 Wk = SP[k * TILE + m];

                ull ttA = mul2(p0A[k], p1p[k]);
                float bA0, bA1; upk(ttA, bA0, bA1);
                ull ebA = pk(ex2(bA0), ex2(bA1));
                ull s0A = fma2(eA01s, Wk.y, mul2(eA00s, Wk.x));
                ull s1A = fma2(eA11s, Wk.y, mul2(eA10s, Wk.x));
                aA0[k] = fma2(ebA, s0A, aA0[k]);
                aA1[k] = fma2(ebA, s1A, aA1[k]);
                sA0[k] = fma2(ebA, esA0s, sA0[k]);
                sA1[k] = fma2(ebA, esA1s, sA1[k]);

                ull ttB = mul2(p0B[k], p1p[k]);
                float bB0, bB1; upk(ttB, bB0, bB1);
                ull ebB = pk(ex2(bB0), ex2(bB1));
                ull s0B = fma2(eB01s, Wk.y, mul2(eB00s, Wk.x));
                ull s1B = fma2(eB11s, Wk.y, mul2(eB10s, Wk.x));
                aB0[k] = fma2(ebB, s0B, aB0[k]);
                aB1[k] = fma2(ebB, s1B, aB1[k]);
                sB0[k] = fma2(ebB, esB0s, sB0[k]);
                sB1[k] = fma2(ebB, esB1s, sB1[k]);
            }
        }
        __syncthreads();
    }

    // warp butterfly reduction
#pragma unroll
    for (int o = 16; o > 0; o >>= 1) {
#pragma unroll
        for (int k = 0; k < 5; k++) {
            aA0[k] = add2(aA0[k], __shfl_xor_sync(0xffffffffu, aA0[k], o));
            aA1[k] = add2(aA1[k], __shfl_xor_sync(0xffffffffu, aA1[k], o));
            sA0[k] = add2(sA0[k], __shfl_xor_sync(0xffffffffu, sA0[k], o));
            sA1[k] = add2(sA1[k], __shfl_xor_sync(0xffffffffu, sA1[k], o));
            aB0[k] = add2(aB0[k], __shfl_xor_sync(0xffffffffu, aB0[k], o));
            aB1[k] = add2(aB1[k], __shfl_xor_sync(0xffffffffu, aB1[k], o));
            sB0[k] = add2(sB0[k], __shfl_xor_sync(0xffffffffu, sB0[k], o));
            sB1[k] = add2(sB1[k], __shfl_xor_sync(0xffffffffu, sB1[k], o));
        }
    }

    if (lane == 0) {
#pragma unroll
        for (int k = 0; k < 5; k++) {
            int c0 = 2 * k, c1 = 2 * k + 1;
            float i0 = g_scinv[b * C_ + c0];
            float i1 = g_scinv[b * C_ + c1];
            float v0, v1, d0, d1;

            upk(aA0[k], v0, v1); upk(sA0[k], d0, d1);
            out[((b * A_ + 0) * C_ + c0) * HW_ + hwnA] = v0 * rcpf(d0) * i0;
            out[((b * A_ + 0) * C_ + c1) * HW_ + hwnA] = v1 * rcpf(d1) * i1;
            upk(aA1[k], v0, v1); upk(sA1[k], d0, d1);
            out[((b * A_ + 1) * C_ + c0) * HW_ + hwnA] = v0 * rcpf(d0) * i0;
            out[((b * A_ + 1) * C_ + c1) * HW_ + hwnA] = v1 * rcpf(d1) * i1;

            upk(aB0[k], v0, v1); upk(sB0[k], d0, d1);
            out[((b * A_ + 0) * C_ + c0) * HW_ + hwnB] = v0 * rcpf(d0) * i0;
            out[((b * A_ + 0) * C_ + c1) * HW_ + hwnB] = v1 * rcpf(d1) * i1;
            upk(aB1[k], v0, v1); upk(sB1[k], d0, d1);
            out[((b * A_ + 1) * C_ + c0) * HW_ + hwnB] = v0 * rcpf(d0) * i0;
            out[((b * A_ + 1) * C_ + c1) * HW_ + hwnB] = v1 * rcpf(d1) * i1;
        }
    }
}

extern "C" void kernel_launch(void* const* d_in, const int* in_sizes, int n_in,
                              void* d_out, int out_size) {
    const float* scores = (const float*)d_in[0];
    const float* bbox = (const float*)d_in[1];
    const float* pp = (const float*)d_in[2];
    const float* dec = (const float*)d_in[3];
    float* out = (float*)d_out;

    k_fused<<<28, 256>>>(scores, pp, dec);
    k_main<<<256 + 88, 128>>>(bbox, pp, out);
}

// round 8
// speedup vs baseline: 1.0703x; 1.0703x over previous
#include <cuda_runtime.h>
#include <cstdint>

// Problem constants
#define BATCH 2
#define A_    2
#define C_    10
#define HW_   1024
#define NBOX  2048
#define TILE  128
#define LOG2E 1.4426950408889634f
#define PI_F  3.14159265358979323846f

// Output layout: out_scores [0,40960) | bbox [40960,69632) | pp [69632,131072)
#define OUT_BBOX 40960
#define OUT_PP   69632

// ---------------- scratch tables (SoA-group layouts) ----------------
// g_bev4: [b][2][HW] float4
//   g0 = (x1a0, x1a1, y1a0, y1a1)   g1 = (x2a0, x2a1, y2a0, y2a1)
__device__ __align__(16) float4 g_bev4[BATCH * 2 * HW_];
// g_pc4: [b][8][HW] float4
//   g=0..4 : (w[2k,a0], w[2k+1,a0], w[2k,a1], w[2k+1,a1])   (w = exp(score))
//   g=5    : (p1[0..3])   g=6 : (p1[4..7])   g=7 : (p1[8],p1[9],area0,area1)
__device__ __align__(16) float4 g_pc4[BATCH * 8 * HW_];
// g_p0: [b*HW][10]  (p0[c] * log2e)
__device__ __align__(8)  float  g_p0[BATCH * HW_ * 10];
__device__ float g_scinv[BATCH * C_];

// ---------------- helpers ----------------
typedef unsigned long long ull;
__device__ __forceinline__ float ex2(float x) {
    float y; asm("ex2.approx.f32 %0, %1;" : "=f"(y) : "f"(x)); return y;
}
__device__ __forceinline__ float rcpf(float x) {
    float y; asm("rcp.approx.f32 %0, %1;" : "=f"(y) : "f"(x)); return y;
}
__device__ __forceinline__ ull pk(float a, float b) {
    ull r; asm("mov.b64 %0, {%1,%2};" : "=l"(r) : "f"(a), "f"(b)); return r;
}
__device__ __forceinline__ void upk(ull v, float& a, float& b) {
    asm("mov.b64 {%0,%1}, %2;" : "=f"(a), "=f"(b) : "l"(v));
}
__device__ __forceinline__ ull mul2(ull a, ull b) {
    ull r; asm("mul.rn.f32x2 %0, %1, %2;" : "=l"(r) : "l"(a), "l"(b)); return r;
}
__device__ __forceinline__ ull fma2(ull a, ull b, ull c) {
    ull r; asm("fma.rn.f32x2 %0, %1, %2, %3;" : "=l"(r) : "l"(a), "l"(b), "l"(c)); return r;
}
__device__ __forceinline__ ull add2(ull a, ull b) {
    ull r; asm("add.rn.f32x2 %0, %1, %2;" : "=l"(r) : "l"(a), "l"(b)); return r;
}
__device__ __forceinline__ void cpasync16(uint32_t saddr, const void* g) {
    asm volatile("cp.async.cg.shared.global [%0], [%1], 16;" :: "r"(saddr), "l"(g));
}

// ---------------------------------------------------------------------------
// K1 fused: prep tables (blocks 0..7) + score softmax denominators (8..27)
// ---------------------------------------------------------------------------
__global__ void k_fused(const float* __restrict__ scores,
                        const float* __restrict__ pp,
                        const float* __restrict__ dec) {
    int blk = blockIdx.x;
    int tid = threadIdx.x;

    if (blk < 8) {
        int idx = blk * 256 + tid;
        int b = idx >> 10;
        int hw = idx & (HW_ - 1);

        float x1a[2], y1a[2], x2a[2], y2a[2], area[2];
#pragma unroll
        for (int a = 0; a < 2; a++) {
            const float* d7 = dec + ((size_t)b * NBOX + hw * 2 + a) * 7;
            float x = d7[0], y = d7[1], dx = d7[3], dy = d7[4], yaw = d7[6];
            float normed = fabsf(yaw - floorf(yaw / PI_F + 0.5f) * PI_F);
            bool sw = normed > 0.25f * PI_F;
            float w = sw ? dy : dx;
            float h = sw ? dx : dy;
            x1a[a] = x - 0.5f * w; y1a[a] = y - 0.5f * h;
            x2a[a] = x + 0.5f * w; y2a[a] = y + 0.5f * h;
            area[a] = (x2a[a] - x1a[a]) * (y2a[a] - y1a[a]);
        }
        float4* bv = g_bev4 + (size_t)b * 2 * HW_ + hw;
        bv[0]    = make_float4(x1a[0], x1a[1], y1a[0], y1a[1]);
        bv[HW_]  = make_float4(x2a[0], x2a[1], y2a[0], y2a[1]);

        float e[C_][2], p1[C_];
#pragma unroll
        for (int c = 0; c < C_; c++) {
            e[c][0] = __expf(scores[((b * A_ + 0) * C_ + c) * HW_ + hw]);
            e[c][1] = __expf(scores[((b * A_ + 1) * C_ + c) * HW_ + hw]);
            p1[c]   = pp[((size_t)b * 30 + c * 3 + 1) * HW_ + hw];
            g_p0[(size_t)idx * 10 + c] =
                pp[((size_t)b * 30 + c * 3) * HW_ + hw] * LOG2E;
        }
        float4* pc = g_pc4 + (size_t)b * 8 * HW_ + hw;
#pragma unroll
        for (int k = 0; k < 5; k++)
            pc[k * HW_] = make_float4(e[2 * k][0], e[2 * k + 1][0],
                                      e[2 * k][1], e[2 * k + 1][1]);
        pc[5 * HW_] = make_float4(p1[0], p1[1], p1[2], p1[3]);
        pc[6 * HW_] = make_float4(p1[4], p1[5], p1[6], p1[7]);
        pc[7 * HW_] = make_float4(p1[8], p1[9], area[0], area[1]);
    } else {
        int s = blk - 8;
        int b = s / C_, c = s % C_;
        __shared__ float red[256];
        float acc = 0.f;
        for (int m = tid; m < NBOX; m += 256) {
            int a = m & 1, hw = m >> 1;
            acc += __expf(scores[((b * A_ + a) * C_ + c) * HW_ + hw]);
        }
        red[tid] = acc;
        __syncthreads();
#pragma unroll
        for (int o = 128; o > 0; o >>= 1) {
            if (tid < o) red[tid] += red[tid + o];
            __syncthreads();
        }
        if (tid == 0) g_scinv[b * C_ + c] = 1.0f / red[0];
    }
}

// ---------------------------------------------------------------------------
// K2 main: one warp per (b,hwn); m-tiles staged in conflict-free SoA smem.
//          Blocks >= 512 do the bbox/pp pass-through copies (overlapped).
// ---------------------------------------------------------------------------
// scalar IoU, returns iou * log2(e)
__device__ __forceinline__ float iou1(float ax1, float ay1, float ax2, float ay2, float aa,
                                      float bx1, float by1, float bx2, float by2, float ba) {
    float ltx = fmaxf(ax1, bx1);
    float lty = fmaxf(ay1, by1);
    float rbx = fminf(ax2, bx2);
    float rby = fminf(ay2, by2);
    float w = fmaxf(rbx - ltx, 0.f);
    float h = fmaxf(rby - lty, 0.f);
    float inter = w * h;
    float uni = fmaxf(aa + ba - inter, 1e-6f);
    return inter * LOG2E * rcpf(uni);
}

__global__ void __launch_bounds__(128, 5) k_main(
        const float* __restrict__ bbox, const float* __restrict__ pp,
        float* __restrict__ out) {
    if (blockIdx.x >= 512) {
        // pass-through copies: 88 blocks * 256 float4 = 22528 f4
        int base = (blockIdx.x - 512) * 256 + threadIdx.x;
#pragma unroll
        for (int r = 0; r < 2; r++) {
            int i = base + r * 128;
            if (i < 7168)
                ((float4*)(out + OUT_BBOX))[i] = ((const float4*)bbox)[i];
            else
                ((float4*)(out + OUT_PP))[i - 7168] = ((const float4*)pp)[i - 7168];
        }
        return;
    }

    __shared__ __align__(16) ulonglong2 sb[2][2 * TILE];  // bev groups
    __shared__ __align__(16) ulonglong2 sp[2][8 * TILE];  // pc groups

    int tid = threadIdx.x;
    int lane = tid & 31;
    int gw = blockIdx.x * 4 + (tid >> 5);
    int b = gw >> 10;
    int hwn = gw & (HW_ - 1);

    // n-side invariants
    float4 ng0 = g_bev4[(size_t)b * 2 * HW_ + hwn];
    float4 ng1 = g_bev4[(size_t)b * 2 * HW_ + HW_ + hwn];
    float4 ng7 = g_pc4[(size_t)b * 8 * HW_ + 7 * HW_ + hwn];
    float n0x1 = ng0.x, n1x1 = ng0.y, n0y1 = ng0.z, n1y1 = ng0.w;
    float n0x2 = ng1.x, n1x2 = ng1.y, n0y2 = ng1.z, n1y2 = ng1.w;
    float an0 = ng7.z, an1 = ng7.w;

    ull p0p[5];
#pragma unroll
    for (int k = 0; k < 5; k++) {
        float2 t = *(const float2*)(g_p0 + (size_t)gw * 10 + 2 * k);
        p0p[k] = pk(t.x, t.y);
    }

    ull acc0p[5], acc1p[5], sm0p[5], sm1p[5];
#pragma unroll
    for (int k = 0; k < 5; k++) { acc0p[k] = 0; acc1p[k] = 0; sm0p[k] = 0; sm1p[k] = 0; }

    const float4* gb = g_bev4 + (size_t)b * 2 * HW_;
    const float4* gp = g_pc4 + (size_t)b * 8 * HW_;

    // prefetch tile 0
    {
        uint32_t sba = (uint32_t)__cvta_generic_to_shared(&sb[0][0]);
        uint32_t spa = (uint32_t)__cvta_generic_to_shared(&sp[0][0]);
#pragma unroll
        for (int g = 0; g < 2; g++)
            cpasync16(sba + (g * TILE + tid) * 16, gb + g * HW_ + tid);
#pragma unroll
        for (int g = 0; g < 8; g++)
            cpasync16(spa + (g * TILE + tid) * 16, gp + g * HW_ + tid);
        asm volatile("cp.async.commit_group;");
    }

    for (int t = 0; t < 8; t++) {
        if (t < 7) {
            int nb = (t + 1) & 1;
            uint32_t sba = (uint32_t)__cvta_generic_to_shared(&sb[nb][0]);
            uint32_t spa = (uint32_t)__cvta_generic_to_shared(&sp[nb][0]);
            int off = (t + 1) * TILE + tid;
#pragma unroll
            for (int g = 0; g < 2; g++)
                cpasync16(sba + (g * TILE + tid) * 16, gb + g * HW_ + off);
#pragma unroll
            for (int g = 0; g < 8; g++)
                cpasync16(spa + (g * TILE + tid) * 16, gp + g * HW_ + off);
            asm volatile("cp.async.commit_group;");
            asm volatile("cp.async.wait_group 1;");
        } else {
            asm volatile("cp.async.wait_group 0;");
        }
        __syncthreads();

        const ulonglong2* SB = sb[t & 1];
        const ulonglong2* SP = sp[t & 1];
#pragma unroll 2
        for (int j = 0; j < 4; j++) {
            int m = lane + j * 32;
            ulonglong2 bg0 = SB[m];            // (x1a0,x1a1) , (y1a0,y1a1)
            ulonglong2 bg1 = SB[TILE + m];     // (x2a0,x2a1) , (y2a0,y2a1)
            ulonglong2 G7  = SP[7 * TILE + m]; // (p1[8],p1[9]) , (area0,area1)

            float bx1a0, bx1a1, by1a0, by1a1, bx2a0, bx2a1, by2a0, by2a1;
            upk(bg0.x, bx1a0, bx1a1);
            upk(bg0.y, by1a0, by1a1);
            upk(bg1.x, bx2a0, bx2a1);
            upk(bg1.y, by2a0, by2a1);
            float am0, am1;
            upk(G7.y, am0, am1);

            float q00 = iou1(n0x1, n0y1, n0x2, n0y2, an0, bx1a0, by1a0, bx2a0, by2a0, am0);
            float q01 = iou1(n0x1, n0y1, n0x2, n0y2, an0, bx1a1, by1a1, bx2a1, by2a1, am1);
            float q10 = iou1(n1x1, n1y1, n1x2, n1y2, an1, bx1a0, by1a0, bx2a0, by2a0, am0);
            float q11 = iou1(n1x1, n1y1, n1x2, n1y2, an1, bx1a1, by1a1, bx2a1, by2a1, am1);

            float e00 = ex2(q00), e01 = ex2(q01);
            float e10 = ex2(q10), e11 = ex2(q11);
            ull e00s = pk(e00, e00), e01s = pk(e01, e01);
            ull e10s = pk(e10, e10), e11s = pk(e11, e11);
            ull es0s = pk(e00 + e01, e00 + e01);
            ull es1s = pk(e10 + e11, e10 + e11);

            ulonglong2 G5 = SP[5 * TILE + m];
            ulonglong2 G6 = SP[6 * TILE + m];
            ull p1p[5] = { G5.x, G5.y, G6.x, G6.y, G7.x };

#pragma unroll
            for (int k = 0; k < 5; k++) {
                ull tt = mul2(p0p[k], p1p[k]);
                float b0, b1; upk(tt, b0, b1);
                ull ebp = pk(ex2(b0), ex2(b1));        // exp(bias) c-pair

                ulonglong2 Wk = SP[k * TILE + m];      // w0p = a0 pair, w1p = a1 pair
                ull s0p = fma2(e01s, Wk.y, mul2(e00s, Wk.x));
                ull s1p = fma2(e11s, Wk.y, mul2(e10s, Wk.x));
                acc0p[k] = fma2(ebp, s0p, acc0p[k]);
                acc1p[k] = fma2(ebp, s1p, acc1p[k]);
                sm0p[k]  = fma2(ebp, es0s, sm0p[k]);
                sm1p[k]  = fma2(ebp, es1s, sm1p[k]);
            }
        }
        __syncthreads();
    }

    // warp butterfly reduction
#pragma unroll
    for (int o = 16; o > 0; o >>= 1) {
#pragma unroll
        for (int k = 0; k < 5; k++) {
            acc0p[k] = add2(acc0p[k], __shfl_xor_sync(0xffffffffu, acc0p[k], o));
            acc1p[k] = add2(acc1p[k], __shfl_xor_sync(0xffffffffu, acc1p[k], o));
            sm0p[k]  = add2(sm0p[k],  __shfl_xor_sync(0xffffffffu, sm0p[k],  o));
            sm1p[k]  = add2(sm1p[k],  __shfl_xor_sync(0xffffffffu, sm1p[k],  o));
        }
    }

    if (lane == 0) {
#pragma unroll
        for (int k = 0; k < 5; k++) {
            float a0, a1, c0v, c1v, q0, q1, r0, r1;
            upk(acc0p[k], a0, a1);
            upk(sm0p[k],  q0, q1);
            upk(acc1p[k], c0v, c1v);
            upk(sm1p[k],  r0, r1);
            int c0 = 2 * k, c1 = 2 * k + 1;
            float i0 = g_scinv[b * C_ + c0];
            float i1 = g_scinv[b * C_ + c1];
            out[((b * A_ + 0) * C_ + c0) * HW_ + hwn] = a0 * rcpf(q0) * i0;
            out[((b * A_ + 0) * C_ + c1) * HW_ + hwn] = a1 * rcpf(q1) * i1;
            out[((b * A_ + 1) * C_ + c0) * HW_ + hwn] = c0v * rcpf(r0) * i0;
            out[((b * A_ + 1) * C_ + c1) * HW_ + hwn] = c1v * rcpf(r1) * i1;
        }
    }
}

extern "C" void kernel_launch(void* const* d_in, const int* in_sizes, int n_in,
                              void* d_out, int out_size) {
    const float* scores = (const float*)d_in[0];
    const float* bbox = (const float*)d_in[1];
    const float* pp = (const float*)d_in[2];
    const float* dec = (const float*)d_in[3];
    float* out = (float*)d_out;

    k_fused<<<28, 256>>>(scores, pp, dec);
    k_main<<<512 + 88, 128>>>(bbox, pp, out);
}